// round 5
// baseline (speedup 1.0000x reference)
#include <cuda_runtime.h>
#include <mma.h>
#include <cstdint>

using namespace nvcuda;

#define TPB   512
#define NT    128          // pixels per block tile
#define C_IN  256
#define HID   64
#define CIN2  96

// ---------------- device scratch: pre-split transposed weights ----------------
// W1t[l][m][k] = W1_l[k][m],  m<64,  k<256   (hi / lo tf32 split)
// W2t[l][m][k] = W2_l[k][m],  m<256, k<96
__device__ float g_W1hi[3][HID * C_IN];
__device__ float g_W1lo[3][HID * C_IN];
__device__ float g_W2hi[3][C_IN * CIN2];
__device__ float g_W2lo[3][C_IN * CIN2];

__device__ __forceinline__ float to_tf32(float v) {
    float r;
    asm("cvt.rna.tf32.f32 %0, %1;" : "=f"(r) : "f"(v));
    return r;
}

__global__ void prep_kernel(const float* __restrict__ W1_0,
                            const float* __restrict__ W1_1,
                            const float* __restrict__ W1_2,
                            const float* __restrict__ W2_0,
                            const float* __restrict__ W2_1,
                            const float* __restrict__ W2_2)
{
    const int idx = blockIdx.x * blockDim.x + threadIdx.x;
    const int N1 = HID * C_IN;          // 16384
    const int N2 = C_IN * CIN2;         // 24576
    if (idx < 3 * N1) {
        const int l = idx / N1, e = idx - l * N1;
        const int m = e / C_IN, k = e - m * C_IN;
        const float* W1 = (l == 0) ? W1_0 : (l == 1) ? W1_1 : W1_2;
        const float v  = W1[k * HID + m];
        const float hi = to_tf32(v);
        g_W1hi[l][m * C_IN + k] = hi;
        g_W1lo[l][m * C_IN + k] = to_tf32(v - hi);
    } else if (idx < 3 * N1 + 3 * N2) {
        const int j = idx - 3 * N1;
        const int l = j / N2, e = j - l * N2;
        const int m = e / CIN2, k = e - m * CIN2;
        const float* W2 = (l == 0) ? W2_0 : (l == 1) ? W2_1 : W2_2;
        const float v  = W2[k * C_IN + m];
        const float hi = to_tf32(v);
        g_W2hi[l][m * CIN2 + k] = hi;
        g_W2lo[l][m * CIN2 + k] = to_tf32(v - hi);
    }
}

// ---------------- smem layout (floats) ----------------
#define SZHI 0                 // Z hi   [96][128]  (also X-chunk staging hi/lo)
#define SZLO 12288             // Z lo   [96][128]
#define SXHI 0                 // X hi   [32][128]  (overlaps SZHI; phase-1 only)
#define SXLO 4096              // X lo   [32][128]
#define SY   24576             // Y      [64][128]  (also output staging)
#define SMEM_FLOATS 32768
#define SMEM_BYTES  (SMEM_FLOATS * 4)   // 131072

typedef wmma::fragment<wmma::matrix_a, 16, 16, 8, wmma::precision::tf32, wmma::row_major> FragA;
typedef wmma::fragment<wmma::matrix_b, 16, 16, 8, wmma::precision::tf32, wmma::row_major> FragB;
typedef wmma::fragment<wmma::accumulator, 16, 16, 8, float> FragC;

__global__ void __launch_bounds__(TPB, 1)
fused_tc_kernel(const float* __restrict__ x0, const float* __restrict__ x1,
                const float* __restrict__ x2,
                const float* __restrict__ b1_0, const float* __restrict__ b2_0,
                const float* __restrict__ b1_1, const float* __restrict__ b2_1,
                const float* __restrict__ b1_2, const float* __restrict__ b2_2,
                float* __restrict__ out)
{
    extern __shared__ float sm[];

    // ---- level select (tiles: 512 | 128 | 32) ----
    const int t = blockIdx.x;
    const float *x, *b1, *b2;
    float* o;
    int npix, tl, lvl;
    if (t < 512) {
        x = x0; b1 = b1_0; b2 = b2_0; o = out;
        npix = 16384; tl = t; lvl = 0;
    } else if (t < 640) {
        x = x1; b1 = b1_1; b2 = b2_1; o = out + 16777216L;
        npix = 4096; tl = t - 512; lvl = 1;
    } else {
        x = x2; b1 = b1_2; b2 = b2_2; o = out + 20971520L;
        npix = 1024; tl = t - 640; lvl = 2;
    }

    const int tid = threadIdx.x;
    const int w   = tid >> 5;
    const int wm  = w & 3;          // M-tile slot
    const int wn  = w >> 2;         // N-group slot (0..3)

    const int tpi  = npix / NT;
    const int img  = tl / tpi;
    const int p0   = (tl - img * tpi) * NT;
    const long ibase = (long)img * C_IN * npix + p0;

    const float* W1hi = g_W1hi[lvl];
    const float* W1lo = g_W1lo[lvl];
    const float* W2hi = g_W2hi[lvl];
    const float* W2lo = g_W2lo[lvl];

    // ================= phase 1: Y[64][128] = W1t @ X  (no bias yet) =================
    {
        FragC acc[2];
        wmma::fill_fragment(acc[0], 0.0f);
        wmma::fill_fragment(acc[1], 0.0f);

        for (int c = 0; c < 8; ++c) {           // K chunks of 32
            // stage X chunk [32][128] hi/lo
            #pragma unroll
            for (int i = 0; i < 2; ++i) {
                const int idx = tid + i * TPB;          // float4 index
                const int row = idx >> 5, c4 = idx & 31;
                const float4 v = *(const float4*)(x + ibase + (long)(c * 32 + row) * npix + (c4 << 2));
                float4 hi, lo;
                hi.x = to_tf32(v.x); lo.x = to_tf32(v.x - hi.x);
                hi.y = to_tf32(v.y); lo.y = to_tf32(v.y - hi.y);
                hi.z = to_tf32(v.z); lo.z = to_tf32(v.z - hi.z);
                hi.w = to_tf32(v.w); lo.w = to_tf32(v.w - hi.w);
                *(float4*)(sm + SXHI + row * 128 + (c4 << 2)) = hi;
                *(float4*)(sm + SXLO + row * 128 + (c4 << 2)) = lo;
            }
            __syncthreads();

            #pragma unroll
            for (int ks = 0; ks < 4; ++ks) {
                FragA fahi, falo;
                const int kof = c * 32 + ks * 8;
                wmma::load_matrix_sync(fahi, W1hi + (wm * 16) * C_IN + kof, C_IN);
                wmma::load_matrix_sync(falo, W1lo + (wm * 16) * C_IN + kof, C_IN);
                #pragma unroll
                for (int nt = 0; nt < 2; ++nt) {
                    const int n0 = (wn * 2 + nt) * 16;
                    FragB fbhi, fblo;
                    wmma::load_matrix_sync(fbhi, sm + SXHI + ks * 8 * 128 + n0, 128);
                    wmma::load_matrix_sync(fblo, sm + SXLO + ks * 8 * 128 + n0, 128);
                    wmma::mma_sync(acc[nt], fahi, fbhi, acc[nt]);
                    wmma::mma_sync(acc[nt], fahi, fblo, acc[nt]);
                    wmma::mma_sync(acc[nt], falo, fbhi, acc[nt]);
                }
            }
            __syncthreads();
        }
        #pragma unroll
        for (int nt = 0; nt < 2; ++nt)
            wmma::store_matrix_sync(sm + SY + (wm * 16) * 128 + (wn * 2 + nt) * 16,
                                    acc[nt], 128, wmma::mem_row_major);
    }
    __syncthreads();

    // ====== build Z[96][128] hi/lo: rows 0..63 = y+b1, 64..95 = relu(y[32..63]+b1) ======
    {
        #pragma unroll
        for (int i = 0; i < 6; ++i) {               // 96*32 float4 / 512
            const int idx = tid + i * TPB;
            const int r = idx >> 5, c4 = idx & 31;
            const int sr = (r < 64) ? r : (r - 32);
            const float bb = b1[sr];
            float4 v = *(const float4*)(sm + SY + sr * 128 + (c4 << 2));
            v.x += bb; v.y += bb; v.z += bb; v.w += bb;
            if (r >= 64) {
                v.x = fmaxf(v.x, 0.f); v.y = fmaxf(v.y, 0.f);
                v.z = fmaxf(v.z, 0.f); v.w = fmaxf(v.w, 0.f);
            }
            float4 hi, lo;
            hi.x = to_tf32(v.x); lo.x = to_tf32(v.x - hi.x);
            hi.y = to_tf32(v.y); lo.y = to_tf32(v.y - hi.y);
            hi.z = to_tf32(v.z); lo.z = to_tf32(v.z - hi.z);
            hi.w = to_tf32(v.w); lo.w = to_tf32(v.w - hi.w);
            *(float4*)(sm + SZHI + r * 128 + (c4 << 2)) = hi;
            *(float4*)(sm + SZLO + r * 128 + (c4 << 2)) = lo;
        }
    }
    __syncthreads();

    // ====== phase 2: O[256][128] = W2t @ Z + b2, flushed 64 rows at a time ======
    for (int mi = 0; mi < 4; ++mi) {
        const int m0 = (mi * 4 + wm) * 16;          // global out-channel base for this warp
        FragC acc[2];
        wmma::fill_fragment(acc[0], 0.0f);
        wmma::fill_fragment(acc[1], 0.0f);

        #pragma unroll
        for (int ks = 0; ks < 12; ++ks) {
            FragA fahi, falo;
            wmma::load_matrix_sync(fahi, W2hi + m0 * CIN2 + ks * 8, CIN2);
            wmma::load_matrix_sync(falo, W2lo + m0 * CIN2 + ks * 8, CIN2);
            #pragma unroll
            for (int nt = 0; nt < 2; ++nt) {
                const int n0 = (wn * 2 + nt) * 16;
                FragB fbhi, fblo;
                wmma::load_matrix_sync(fbhi, sm + SZHI + ks * 8 * 128 + n0, 128);
                wmma::load_matrix_sync(fblo, sm + SZLO + ks * 8 * 128 + n0, 128);
                wmma::mma_sync(acc[nt], fahi, fbhi, acc[nt]);
                wmma::mma_sync(acc[nt], fahi, fblo, acc[nt]);
                wmma::mma_sync(acc[nt], falo, fbhi, acc[nt]);
            }
        }

        // stage 64 rows (this mi covers out-channels mi*64 .. mi*64+63)
        #pragma unroll
        for (int nt = 0; nt < 2; ++nt)
            wmma::store_matrix_sync(sm + SY + (wm * 16) * 128 + (wn * 2 + nt) * 16,
                                    acc[nt], 128, wmma::mem_row_major);
        __syncthreads();

        // copy staging -> gmem with bias
        #pragma unroll
        for (int i = 0; i < 4; ++i) {               // 64*32 float4 / 512
            const int idx = tid + i * TPB;
            const int r = idx >> 5, c4 = idx & 31;
            const int gm = mi * 64 + r;
            const float bb = b2[gm];
            float4 v = *(const float4*)(sm + SY + r * 128 + (c4 << 2));
            v.x += bb; v.y += bb; v.z += bb; v.w += bb;
            *(float4*)(o + ibase + (long)gm * npix + (c4 << 2)) = v;
        }
        __syncthreads();
    }
}

extern "C" void kernel_launch(void* const* d_in, const int* in_sizes, int n_in,
                              void* d_out, int out_size)
{
    const float* x0   = (const float*)d_in[0];
    const float* x1   = (const float*)d_in[1];
    const float* x2   = (const float*)d_in[2];
    const float* W1_0 = (const float*)d_in[3];
    const float* b1_0 = (const float*)d_in[4];
    const float* W2_0 = (const float*)d_in[5];
    const float* b2_0 = (const float*)d_in[6];
    const float* W1_1 = (const float*)d_in[7];
    const float* b1_1 = (const float*)d_in[8];
    const float* W2_1 = (const float*)d_in[9];
    const float* b2_1 = (const float*)d_in[10];
    const float* W1_2 = (const float*)d_in[11];
    const float* b1_2 = (const float*)d_in[12];
    const float* W2_2 = (const float*)d_in[13];
    const float* b2_2 = (const float*)d_in[14];

    // split + transpose weights into device scratch
    const int total = 3 * (HID * C_IN) + 3 * (C_IN * CIN2);   // 122880
    prep_kernel<<<(total + 255) / 256, 256>>>(W1_0, W1_1, W1_2, W2_0, W2_1, W2_2);

    cudaFuncSetAttribute(fused_tc_kernel,
                         cudaFuncAttributeMaxDynamicSharedMemorySize, SMEM_BYTES);

    fused_tc_kernel<<<672, TPB, SMEM_BYTES>>>(
        x0, x1, x2,
        b1_0, b2_0, b1_1, b2_1, b1_2, b2_2,
        (float*)d_out);
}

// round 7
// speedup vs baseline: 5.8834x; 5.8834x over previous
#include <cuda_runtime.h>
#include <cuda_bf16.h>
#include <cstdint>

#define TPB  512
#define NT   128
#define C_IN 256

// ---------------- smem byte offsets (total 131072) ----------------
#define XH_OFF   0u        // X hi frags  [16ks][16nt][32] uint2 = 65536
#define XL_OFF   65536u    // X lo frags
#define SC_OFF   0u        // y scratch 64 x 132 f32 = 33792 (reuses X region)
#define ZH_OFF   33792u    // Z hi frags  [6ks][16nt][32] uint2 = 24576
#define ZL_OFF   58368u    // Z lo frags
#define SMEM_BYTES 131072u

// ---------------- fragment-ordered weights (prep output) ----------------
// A1[l][mt(4)][ks(16)][lane] : uint4 (a0..a3), hi and lo
// A2[l][mt(16)][ks(6)][lane] : uint4
__device__ uint4 g_A1h[3 * 4 * 16 * 32];
__device__ uint4 g_A1l[3 * 4 * 16 * 32];
__device__ uint4 g_A2h[3 * 16 * 6 * 32];
__device__ uint4 g_A2l[3 * 16 * 6 * 32];

__device__ __forceinline__ void split_bf(float v, unsigned short& h, unsigned short& l) {
    __nv_bfloat16 bh = __float2bfloat16_rn(v);
    h = __bfloat16_as_ushort(bh);
    l = __bfloat16_as_ushort(__float2bfloat16_rn(v - __bfloat162float(bh)));
}
__device__ __forceinline__ unsigned pack2u(unsigned short a, unsigned short b) {
    return (unsigned)a | ((unsigned)b << 16);
}

// mma.sync m16n8k16 row.col f32.bf16.bf16.f32
__device__ __forceinline__ void mma_bf(float* c, const uint4& a, const uint2& b) {
    asm volatile(
        "mma.sync.aligned.m16n8k16.row.col.f32.bf16.bf16.f32 "
        "{%0,%1,%2,%3}, {%4,%5,%6,%7}, {%8,%9}, {%0,%1,%2,%3};"
        : "+f"(c[0]), "+f"(c[1]), "+f"(c[2]), "+f"(c[3])
        : "r"(a.x), "r"(a.y), "r"(a.z), "r"(a.w), "r"(b.x), "r"(b.y));
}

// ---------------- prep: fragment + split weights ----------------
__global__ void prep_kernel(const float* __restrict__ W1_0, const float* __restrict__ W1_1,
                            const float* __restrict__ W1_2,
                            const float* __restrict__ W2_0, const float* __restrict__ W2_1,
                            const float* __restrict__ W2_2)
{
    const int idx = blockIdx.x * blockDim.x + threadIdx.x;
    const int N1 = 3 * 4 * 16 * 32;          // 6144
    const int N2 = 3 * 16 * 6 * 32;          // 9216
    if (idx < N1) {
        const int lane = idx & 31, ks = (idx >> 5) & 15, mt = (idx >> 9) & 3, l = idx >> 11;
        const float* W1 = (l == 0) ? W1_0 : (l == 1) ? W1_1 : W1_2;
        const int r0 = mt * 16 + (lane >> 2);
        const int c0 = ks * 16 + (lane & 3) * 2;
        // A[m][k] = W1[k*64 + m]
        unsigned short h[8], lo[8];
        split_bf(W1[(c0    ) * 64 + r0    ], h[0], lo[0]);
        split_bf(W1[(c0 + 1) * 64 + r0    ], h[1], lo[1]);
        split_bf(W1[(c0    ) * 64 + r0 + 8], h[2], lo[2]);
        split_bf(W1[(c0 + 1) * 64 + r0 + 8], h[3], lo[3]);
        split_bf(W1[(c0 + 8) * 64 + r0    ], h[4], lo[4]);
        split_bf(W1[(c0 + 9) * 64 + r0    ], h[5], lo[5]);
        split_bf(W1[(c0 + 8) * 64 + r0 + 8], h[6], lo[6]);
        split_bf(W1[(c0 + 9) * 64 + r0 + 8], h[7], lo[7]);
        g_A1h[idx] = make_uint4(pack2u(h[0], h[1]), pack2u(h[2], h[3]),
                                pack2u(h[4], h[5]), pack2u(h[6], h[7]));
        g_A1l[idx] = make_uint4(pack2u(lo[0], lo[1]), pack2u(lo[2], lo[3]),
                                pack2u(lo[4], lo[5]), pack2u(lo[6], lo[7]));
    } else if (idx < N1 + N2) {
        const int i2 = idx - N1;
        const int lane = i2 & 31;
        const int rest = i2 >> 5;            // 0..287
        const int ks = rest % 6;
        const int mt = (rest / 6) & 15;
        const int l  = rest / 96;
        const float* W2 = (l == 0) ? W2_0 : (l == 1) ? W2_1 : W2_2;
        const int r0 = mt * 16 + (lane >> 2);
        const int c0 = ks * 16 + (lane & 3) * 2;
        // A[m][k] = W2[k*256 + m]
        unsigned short h[8], lo[8];
        split_bf(W2[(c0    ) * 256 + r0    ], h[0], lo[0]);
        split_bf(W2[(c0 + 1) * 256 + r0    ], h[1], lo[1]);
        split_bf(W2[(c0    ) * 256 + r0 + 8], h[2], lo[2]);
        split_bf(W2[(c0 + 1) * 256 + r0 + 8], h[3], lo[3]);
        split_bf(W2[(c0 + 8) * 256 + r0    ], h[4], lo[4]);
        split_bf(W2[(c0 + 9) * 256 + r0    ], h[5], lo[5]);
        split_bf(W2[(c0 + 8) * 256 + r0 + 8], h[6], lo[6]);
        split_bf(W2[(c0 + 9) * 256 + r0 + 8], h[7], lo[7]);
        g_A2h[i2] = make_uint4(pack2u(h[0], h[1]), pack2u(h[2], h[3]),
                               pack2u(h[4], h[5]), pack2u(h[6], h[7]));
        g_A2l[i2] = make_uint4(pack2u(lo[0], lo[1]), pack2u(lo[2], lo[3]),
                               pack2u(lo[4], lo[5]), pack2u(lo[6], lo[7]));
    }
}

__global__ void __launch_bounds__(TPB, 1)
fused_mma_kernel(const float* __restrict__ x0, const float* __restrict__ x1,
                 const float* __restrict__ x2,
                 const float* __restrict__ b1_0, const float* __restrict__ b2_0,
                 const float* __restrict__ b1_1, const float* __restrict__ b2_1,
                 const float* __restrict__ b1_2, const float* __restrict__ b2_2,
                 float* __restrict__ out)
{
    extern __shared__ char smc[];
    const int tid  = threadIdx.x;
    const int w    = tid >> 5;
    const int lane = tid & 31;

    // ---- level select (tiles: 512 | 128 | 32) ----
    const int t = blockIdx.x;
    const float *x, *b1, *b2;
    float* o;
    int npix, tl, lvl;
    if (t < 512)      { x = x0; b1 = b1_0; b2 = b2_0; o = out;             npix = 16384; tl = t;       lvl = 0; }
    else if (t < 640) { x = x1; b1 = b1_1; b2 = b2_1; o = out + 16777216L; npix = 4096;  tl = t - 512; lvl = 1; }
    else              { x = x2; b1 = b1_2; b2 = b2_2; o = out + 20971520L; npix = 1024;  tl = t - 640; lvl = 2; }

    const int tpi  = npix / NT;
    const int img  = tl / tpi;
    const int p0   = (tl - img * tpi) * NT;
    const long ibase = (long)img * C_IN * npix + p0;

    uint2* sXh = (uint2*)(smc + XH_OFF);
    uint2* sXl = (uint2*)(smc + XL_OFF);
    uint2* sZh = (uint2*)(smc + ZH_OFF);
    uint2* sZl = (uint2*)(smc + ZL_OFF);
    float* sSc = (float*)(smc + SC_OFF);

    // ================= stage X fragments (hi/lo) =================
    // item: kp(4) | j(2) | nt(16) | ks(16)  -> 2048 items
    #pragma unroll
    for (int it = 0; it < 4; ++it) {
        const int idx = tid + it * TPB;
        const int kp = idx & 3, j = (idx >> 2) & 1, nt = (idx >> 3) & 15, ks = idx >> 7;
        const int c0 = ks * 16 + 2 * kp;
        const int p  = nt * 8 + 4 * j;
        const float4 r0 = *(const float4*)(x + ibase + (long)(c0    ) * npix + p);
        const float4 r1 = *(const float4*)(x + ibase + (long)(c0 + 1) * npix + p);
        const float4 r2 = *(const float4*)(x + ibase + (long)(c0 + 8) * npix + p);
        const float4 r3 = *(const float4*)(x + ibase + (long)(c0 + 9) * npix + p);
        const float v0[4] = {r0.x, r0.y, r0.z, r0.w};
        const float v1[4] = {r1.x, r1.y, r1.z, r1.w};
        const float v2[4] = {r2.x, r2.y, r2.z, r2.w};
        const float v3[4] = {r3.x, r3.y, r3.z, r3.w};
        const int base = (ks * 16 + nt) * 32;
        #pragma unroll
        for (int q = 0; q < 4; ++q) {
            unsigned short h0, l0, h1, l1, h2, l2, h3, l3;
            split_bf(v0[q], h0, l0); split_bf(v1[q], h1, l1);
            split_bf(v2[q], h2, l2); split_bf(v3[q], h3, l3);
            const int lp = base + (4 * j + q) * 4 + kp;
            sXh[lp] = make_uint2(pack2u(h0, h1), pack2u(h2, h3));
            sXl[lp] = make_uint2(pack2u(l0, l1), pack2u(l2, l3));
        }
    }
    __syncthreads();

    // ================= phase 1 MMA: warp slot (mt = w&3, nq = w>>2) =================
    float acc1[16];
    {
        const int mt = w & 3, nq = w >> 2;
        #pragma unroll
        for (int i = 0; i < 16; ++i) acc1[i] = 0.0f;
        const uint4* Ah = g_A1h + ((lvl * 4 + mt) * 16) * 32 + lane;
        const uint4* Al = g_A1l + ((lvl * 4 + mt) * 16) * 32 + lane;
        #pragma unroll 4
        for (int ks = 0; ks < 16; ++ks) {
            const uint4 ah = __ldg(Ah + ks * 32);
            const uint4 al = __ldg(Al + ks * 32);
            #pragma unroll
            for (int nt8 = 0; nt8 < 4; ++nt8) {
                const int nt = nq * 4 + nt8;
                const uint2 bh = sXh[(ks * 16 + nt) * 32 + lane];
                const uint2 bl = sXl[(ks * 16 + nt) * 32 + lane];
                mma_bf(acc1 + nt8 * 4, ah, bh);
                mma_bf(acc1 + nt8 * 4, ah, bl);
                mma_bf(acc1 + nt8 * 4, al, bh);
            }
        }
    }
    __syncthreads();   // all X-frag reads done before scratch overlays the region

    // ---- phase-1 epilogue: y = acc + b1 -> scratch [64][132] ----
    {
        const int mt = w & 3, nq = w >> 2;
        const int r0 = mt * 16 + (lane >> 2), r1 = r0 + 8;
        const float bias0 = __ldg(b1 + r0);
        const float bias1 = __ldg(b1 + r1);
        #pragma unroll
        for (int nt8 = 0; nt8 < 4; ++nt8) {
            const int col = nq * 32 + nt8 * 8 + (lane & 3) * 2;
            *(float2*)(sSc + r0 * 132 + col) = make_float2(acc1[nt8 * 4 + 0] + bias0,
                                                           acc1[nt8 * 4 + 1] + bias0);
            *(float2*)(sSc + r1 * 132 + col) = make_float2(acc1[nt8 * 4 + 2] + bias1,
                                                           acc1[nt8 * 4 + 3] + bias1);
        }
    }
    __syncthreads();

    // ---- build Z fragments: rows 0..63 = y, 64..95 = relu(y[32..63]) ----
    #pragma unroll
    for (int it = 0; it < 2; ++it) {
        const int idx = tid + it * TPB;
        if (idx < 768) {
            const int kp = idx & 3, j = (idx >> 2) & 1, nt = (idx >> 3) & 15, ks = idx >> 7;
            const int p = nt * 8 + 4 * j;
            float v[4][4];
            #pragma unroll
            for (int e = 0; e < 4; ++e) {
                const int zc = ks * 16 + 2 * kp + ((e >> 1) ? 8 : 0) + (e & 1);
                const int yr = (zc < 64) ? zc : (zc - 32);
                float4 yv = *(const float4*)(sSc + yr * 132 + p);
                if (zc >= 64) {
                    yv.x = fmaxf(yv.x, 0.f); yv.y = fmaxf(yv.y, 0.f);
                    yv.z = fmaxf(yv.z, 0.f); yv.w = fmaxf(yv.w, 0.f);
                }
                v[e][0] = yv.x; v[e][1] = yv.y; v[e][2] = yv.z; v[e][3] = yv.w;
            }
            const int base = (ks * 16 + nt) * 32;
            #pragma unroll
            for (int q = 0; q < 4; ++q) {
                unsigned short h0, l0, h1, l1, h2, l2, h3, l3;
                split_bf(v[0][q], h0, l0); split_bf(v[1][q], h1, l1);
                split_bf(v[2][q], h2, l2); split_bf(v[3][q], h3, l3);
                const int lp = base + (4 * j + q) * 4 + kp;
                sZh[lp] = make_uint2(pack2u(h0, h1), pack2u(h2, h3));
                sZl[lp] = make_uint2(pack2u(l0, l1), pack2u(l2, l3));
            }
        }
    }
    __syncthreads();

    // ================= phase 2 MMA: warp = mt (0..15), full N=128 =================
    float acc2[64];
    {
        #pragma unroll
        for (int i = 0; i < 64; ++i) acc2[i] = 0.0f;
        const uint4* Ah = g_A2h + ((lvl * 16 + w) * 6) * 32 + lane;
        const uint4* Al = g_A2l + ((lvl * 16 + w) * 6) * 32 + lane;
        #pragma unroll 1
        for (int ks = 0; ks < 6; ++ks) {
            const uint4 ah = __ldg(Ah + ks * 32);
            const uint4 al = __ldg(Al + ks * 32);
            #pragma unroll
            for (int nt = 0; nt < 16; ++nt) {
                const uint2 bh = sZh[(ks * 16 + nt) * 32 + lane];
                const uint2 bl = sZl[(ks * 16 + nt) * 32 + lane];
                mma_bf(acc2 + nt * 4, ah, bh);
                mma_bf(acc2 + nt * 4, ah, bl);
                mma_bf(acc2 + nt * 4, al, bh);
            }
        }
    }

    // ---- phase-2 epilogue: O = acc + b2 -> gmem ----
    {
        const int ch0 = w * 16 + (lane >> 2), ch1 = ch0 + 8;
        const float bias0 = __ldg(b2 + ch0);
        const float bias1 = __ldg(b2 + ch1);
        float* o0 = o + ibase + (long)ch0 * npix;
        float* o1 = o + ibase + (long)ch1 * npix;
        #pragma unroll
        for (int nt = 0; nt < 16; ++nt) {
            const int px = nt * 8 + (lane & 3) * 2;
            *(float2*)(o0 + px) = make_float2(acc2[nt * 4 + 0] + bias0,
                                              acc2[nt * 4 + 1] + bias0);
            *(float2*)(o1 + px) = make_float2(acc2[nt * 4 + 2] + bias1,
                                              acc2[nt * 4 + 3] + bias1);
        }
    }
}

extern "C" void kernel_launch(void* const* d_in, const int* in_sizes, int n_in,
                              void* d_out, int out_size)
{
    const float* x0   = (const float*)d_in[0];
    const float* x1   = (const float*)d_in[1];
    const float* x2   = (const float*)d_in[2];
    const float* W1_0 = (const float*)d_in[3];
    const float* b1_0 = (const float*)d_in[4];
    const float* W2_0 = (const float*)d_in[5];
    const float* b2_0 = (const float*)d_in[6];
    const float* W1_1 = (const float*)d_in[7];
    const float* b1_1 = (const float*)d_in[8];
    const float* W2_1 = (const float*)d_in[9];
    const float* b2_1 = (const float*)d_in[10];
    const float* W1_2 = (const float*)d_in[11];
    const float* b1_2 = (const float*)d_in[12];
    const float* W2_2 = (const float*)d_in[13];
    const float* b2_2 = (const float*)d_in[14];

    const int total = 3 * 4 * 16 * 32 + 3 * 16 * 6 * 32;   // 15360
    prep_kernel<<<(total + 255) / 256, 256>>>(W1_0, W1_1, W1_2, W2_0, W2_1, W2_2);

    cudaFuncSetAttribute(fused_mma_kernel,
                         cudaFuncAttributeMaxDynamicSharedMemorySize, SMEM_BYTES);

    fused_mma_kernel<<<672, TPB, SMEM_BYTES>>>(
        x0, x1, x2,
        b1_0, b2_0, b1_1, b2_1, b1_2, b2_2,
        (float*)d_out);
}